// round 4
// baseline (speedup 1.0000x reference)
#include <cuda_runtime.h>
#include <cstdint>

typedef unsigned long long ull;

// Problem constants
#define DDIM 4096
#define NEXP 64
#define NTOK 16384          // B*S
#define BM   128
#define BK   32
#define NSTAGE (DDIM / BK)  // 128
#define NCTA (NTOK / BM)    // 128

// Output layout (tuple flattened to float32 in reference order)
#define IDX_OFF   0
#define SC_OFF    32768
#define PB_OFF    65536
#define Z_OFF     1114112
#define IMP_OFF   1114113
#define LOAD_OFF  1114177

// Per-CTA partial stats: [0..63] importance, [64..127] counts, [128] z^2
__device__ float g_part[NCTA][129];
__device__ unsigned int g_ctr = 0;   // self-resetting via atomicInc wrap

// ---------- PTX helpers ----------
__device__ __forceinline__ ull ffma2(ull a, ull b, ull c) {
    ull d;
    asm("fma.rn.f32x2 %0, %1, %2, %3;" : "=l"(d) : "l"(a), "l"(b), "l"(c));
    return d;
}
__device__ __forceinline__ void cp8(uint32_t dst, const void* src) {
    asm volatile("cp.async.ca.shared.global [%0], [%1], 8;" :: "r"(dst), "l"(src));
}
__device__ __forceinline__ void cp_commit() {
    asm volatile("cp.async.commit_group;" ::: "memory");
}
template <int N> __device__ __forceinline__ void cp_wait() {
    asm volatile("cp.async.wait_group %0;" :: "n"(N) : "memory");
}

// ---------- single fused kernel ----------
// grid = 128 CTAs (one per 128-token tile), block = 128 threads.
extern "C" __global__ void __launch_bounds__(128)
router_kernel(const float* __restrict__ x, const float* __restrict__ W,
              float* __restrict__ out) {
    // 12288 floats = 48KB static smem.
    //   xs0 [0..4095], ws0 [4096..6143], xs1 [6144..10239], ws1 [10240..12287]
    // After mainloop: ls (128x65 = 8320 floats) at sm[0..8319], stats at sm[8320..8448]
    __shared__ float sm[12288];
    float* xs[2] = { sm,        sm + 6144 };
    float* ws[2] = { sm + 4096, sm + 10240 };
    uint32_t xs_a[2], ws_a[2];
    xs_a[0] = (uint32_t)__cvta_generic_to_shared(xs[0]);
    xs_a[1] = (uint32_t)__cvta_generic_to_shared(xs[1]);
    ws_a[0] = (uint32_t)__cvta_generic_to_shared(ws[0]);
    ws_a[1] = (uint32_t)__cvta_generic_to_shared(ws[1]);

    const int tid = threadIdx.x;
    const int tm = tid & 15;      // row group (16)
    const int tn = tid >> 4;      // expert group (8)
    const int rowbase = blockIdx.x * BM;

    // ---- stage loader: both x and W pair-swizzled (pair kc stored at kc^(row&15)) ----
    auto load_stage = [&](int s, int b) {
        const float* xg = x + (size_t)rowbase * DDIM + s * BK;
        #pragma unroll
        for (int i = 0; i < 16; i++) {
            int c = tid + 128 * i;          // 128 rows x 16 pairs
            int r = c >> 4;
            int kc = c & 15;
            uint32_t dst = xs_a[b] + (uint32_t)((r * 32 + ((kc ^ (r & 15)) << 1)) * 4);
            cp8(dst, xg + (size_t)r * DDIM + (kc << 1));
        }
        const float* wg = W + s * BK;
        #pragma unroll
        for (int i = 0; i < 8; i++) {
            int c = tid + 128 * i;          // 64 rows x 16 pairs
            int r = c >> 4;
            int kc = c & 15;
            uint32_t dst = ws_a[b] + (uint32_t)((r * 32 + ((kc ^ (r & 15)) << 1)) * 4);
            cp8(dst, wg + (size_t)r * DDIM + (kc << 1));
        }
        cp_commit();
    };

    ull acc[8][8];
    #pragma unroll
    for (int i = 0; i < 8; i++)
        #pragma unroll
        for (int j = 0; j < 8; j++) acc[i][j] = 0ull;

    load_stage(0, 0);

    #pragma unroll 1
    for (int s = 0; s < NSTAGE; s++) {
        if (s + 1 < NSTAGE) {
            load_stage(s + 1, (s + 1) & 1);
            cp_wait<1>();
        } else {
            cp_wait<0>();
        }
        __syncthreads();

        const float* X  = xs[s & 1];
        const float* Wm = ws[s & 1];
        const float* Xr = X + tm * 32;   // this thread's x row base
        const float* Wr = Wm + tn * 32;  // this thread's w row base

        #pragma unroll 2
        for (int kp = 0; kp < 16; kp++) {
            // de-swizzle offsets (row&15 is tm for x rows; tn / tn+8 alternating for w rows)
            const ull* xp  = (const ull*)(Xr + ((kp ^ tm) << 1));
            const ull* wp0 = (const ull*)(Wr + ((kp ^ tn) << 1));
            const ull* wp1 = (const ull*)(Wr + ((kp ^ (tn + 8)) << 1));
            ull xv[8], wv[8];
            #pragma unroll
            for (int i = 0; i < 8; i++) xv[i] = xp[i * 256];          // +16 rows
            #pragma unroll
            for (int j = 0; j < 8; j++)
                wv[j] = ((j & 1) ? wp1 : wp0)[j * 128];               // +8 rows
            #pragma unroll
            for (int i = 0; i < 8; i++)
                #pragma unroll
                for (int j = 0; j < 8; j++)
                    acc[i][j] = ffma2(xv[i], wv[j], acc[i][j]);
        }
        __syncthreads();
    }

    // ---- epilogue: logits -> smem (stride 65 to kill STS bank conflicts) ----
    float* ls = sm;                 // [128][65]
    float* st = sm + 8320;          // [129] CTA stats
    #pragma unroll
    for (int i = 0; i < 8; i++)
        #pragma unroll
        for (int j = 0; j < 8; j++) {
            float lo = __uint_as_float((uint32_t)(acc[i][j] & 0xffffffffull));
            float hi = __uint_as_float((uint32_t)(acc[i][j] >> 32));
            ls[(tm + 16 * i) * 65 + (tn + 8 * j)] = lo + hi;
        }
    st[tid] = 0.0f;
    if (tid == 0) st[128] = 0.0f;   // block has 128 threads; slot 128 needs explicit zero
    __syncthreads();

    // ---- router: one warp per 32 rows ----
    const int warp = tid >> 5;
    const int lane = tid & 31;
    const float NEG_INF = __int_as_float(0xff800000u);
    float imp0 = 0.f, imp1 = 0.f, cnt0 = 0.f, cnt1 = 0.f, z2 = 0.f;
    float* probs_out = out + PB_OFF;

    #pragma unroll 2
    for (int it = 0; it < 32; it++) {
        const int rl = warp * 32 + it;
        const int row = rowbase + rl;
        const float va = ls[rl * 65 + lane];
        const float vb = ls[rl * 65 + lane + 32];

        // top-1 (ties -> lower index)
        float bv; int bi;
        if (va >= vb) { bv = va; bi = lane; } else { bv = vb; bi = lane + 32; }
        #pragma unroll
        for (int off = 16; off; off >>= 1) {
            float ov = __shfl_xor_sync(0xffffffffu, bv, off);
            int   oi = __shfl_xor_sync(0xffffffffu, bi, off);
            if (ov > bv || (ov == bv && oi < bi)) { bv = ov; bi = oi; }
        }
        // top-2 (exclude bi)
        float va2 = (lane == bi)      ? NEG_INF : va;
        float vb2 = (lane + 32 == bi) ? NEG_INF : vb;
        float sv; int si;
        if (va2 >= vb2) { sv = va2; si = lane; } else { sv = vb2; si = lane + 32; }
        #pragma unroll
        for (int off = 16; off; off >>= 1) {
            float ov = __shfl_xor_sync(0xffffffffu, sv, off);
            int   oi = __shfl_xor_sync(0xffffffffu, si, off);
            if (ov > sv || (ov == sv && oi < si)) { sv = ov; si = oi; }
        }

        // full softmax (max-shifted)
        const float ea = __expf(va - bv);
        const float eb = __expf(vb - bv);
        float ssum = ea + eb;
        #pragma unroll
        for (int off = 16; off; off >>= 1)
            ssum += __shfl_xor_sync(0xffffffffu, ssum, off);
        const float inv = 1.0f / ssum;
        const float pa = ea * inv, pb = eb * inv;

        probs_out[(size_t)row * 64 + lane]      = pa;
        probs_out[(size_t)row * 64 + lane + 32] = pb;

        imp0 += pa; imp1 += pb;
        cnt0 += (bi == lane      ? 1.f : 0.f) + (si == lane      ? 1.f : 0.f);
        cnt1 += (bi == lane + 32 ? 1.f : 0.f) + (si == lane + 32 ? 1.f : 0.f);

        if (lane == 0) {
            const float z = bv + __logf(ssum);
            z2 += z * z;
            out[IDX_OFF + row * 2]     = (float)bi;
            out[IDX_OFF + row * 2 + 1] = (float)si;
            const float e2 = __expf(sv - bv);
            const float dn = 1.0f / (1.0f + e2);
            out[SC_OFF + row * 2]     = dn;
            out[SC_OFF + row * 2 + 1] = e2 * dn;
        }
    }

    // ---- CTA-level stats reduce in smem, then one row of g_part ----
    atomicAdd(&st[lane],      imp0);
    atomicAdd(&st[lane + 32], imp1);
    atomicAdd(&st[64 + lane], cnt0);
    atomicAdd(&st[96 + lane], cnt1);
    if (lane == 0) atomicAdd(&st[128], z2);
    __syncthreads();

    g_part[blockIdx.x][tid] = st[tid];
    if (tid == 0) g_part[blockIdx.x][128] = st[128];   // slot 128 too

    // ---- last-CTA finalize (self-resetting counter) ----
    __shared__ unsigned int s_last;
    __threadfence();
    __syncthreads();
    if (tid == 0) {
        unsigned int old = atomicInc(&g_ctr, NCTA - 1);
        s_last = (old == NCTA - 1) ? 1u : 0u;
    }
    __syncthreads();
    if (s_last) {
        __threadfence();
        #pragma unroll 1
        for (int e = tid; e < 129; e += 128) {
            float ssum = 0.f;
            #pragma unroll 1
            for (int c = 0; c < NCTA; c++) ssum += g_part[c][e];
            if (e < 64)       out[IMP_OFF + e]         = ssum * (1.0f / 16384.0f);
            else if (e < 128) out[LOAD_OFF + (e - 64)] = ssum * (1.0f / 32768.0f);
            else              out[Z_OFF]               = ssum * (1.0f / 16384.0f);
        }
    }
}

extern "C" void kernel_launch(void* const* d_in, const int* in_sizes, int n_in,
                              void* d_out, int out_size) {
    const float* x = (const float*)d_in[0];   // [4,4096,4096] f32
    const float* W = (const float*)d_in[1];   // [64,4096] f32
    float* out = (float*)d_out;
    (void)in_sizes; (void)n_in; (void)out_size;
    router_kernel<<<NCTA, 128>>>(x, W, out);
}

// round 5
// speedup vs baseline: 1.2121x; 1.2121x over previous
#include <cuda_runtime.h>
#include <cstdint>

typedef unsigned long long ull;

// Problem constants
#define DDIM 4096
#define NEXP 64
#define NTOK 16384          // B*S
#define BM   128
#define BK   32
#define NSTAGE (DDIM / BK)  // 128
#define NCTA (NTOK / BM)    // 128

// Output layout (tuple flattened to float32 in reference order)
#define IDX_OFF   0
#define SC_OFF    32768
#define PB_OFF    65536
#define Z_OFF     1114112
#define IMP_OFF   1114113
#define LOAD_OFF  1114177

// Per-CTA partial stats: [0..63] importance, [64..127] counts, [128] z^2
__device__ float g_part[NCTA][129];
__device__ unsigned int g_ctr = 0;   // self-resetting via atomicInc wrap

// ---------- PTX helpers ----------
__device__ __forceinline__ ull ffma2(ull a, ull b, ull c) {
    ull d;
    asm("fma.rn.f32x2 %0, %1, %2, %3;" : "=l"(d) : "l"(a), "l"(b), "l"(c));
    return d;
}
__device__ __forceinline__ void cp8(uint32_t dst, const void* src) {
    asm volatile("cp.async.ca.shared.global [%0], [%1], 8;" :: "r"(dst), "l"(src));
}
__device__ __forceinline__ void cp_commit() {
    asm volatile("cp.async.commit_group;" ::: "memory");
}
template <int N> __device__ __forceinline__ void cp_wait() {
    asm volatile("cp.async.wait_group %0;" :: "n"(N) : "memory");
}

// ---------- single fused kernel ----------
// grid = 128 CTAs (one per 128-token tile), block = 128 threads, 1 CTA/SM.
// Strategy: single warp/SMSP, but fully software-pipelined operand loads so the
// FFMA2 pipe (rt_SMSP=2) stays saturated.
extern "C" __global__ void __launch_bounds__(128, 1)
router_kernel(const float* __restrict__ x, const float* __restrict__ W,
              float* __restrict__ out) {
    // 12288 floats = 48KB static smem.
    __shared__ float sm[12288];
    float* xs[2] = { sm,        sm + 6144 };
    float* ws[2] = { sm + 4096, sm + 10240 };
    uint32_t xs_a[2], ws_a[2];
    xs_a[0] = (uint32_t)__cvta_generic_to_shared(xs[0]);
    xs_a[1] = (uint32_t)__cvta_generic_to_shared(xs[1]);
    ws_a[0] = (uint32_t)__cvta_generic_to_shared(ws[0]);
    ws_a[1] = (uint32_t)__cvta_generic_to_shared(ws[1]);

    const int tid = threadIdx.x;
    const int tm = tid & 15;      // row group (16)
    const int tn = tid >> 4;      // expert group (8)
    const int rowbase = blockIdx.x * BM;

    // ---- stage loader: both x and W pair-swizzled (pair kc stored at kc^(row&15)) ----
    auto load_stage = [&](int s, int b) {
        const float* xg = x + (size_t)rowbase * DDIM + s * BK;
        #pragma unroll
        for (int i = 0; i < 16; i++) {
            int c = tid + 128 * i;          // 128 rows x 16 pairs
            int r = c >> 4;
            int kc = c & 15;
            uint32_t dst = xs_a[b] + (uint32_t)((r * 32 + ((kc ^ (r & 15)) << 1)) * 4);
            cp8(dst, xg + (size_t)r * DDIM + (kc << 1));
        }
        const float* wg = W + s * BK;
        #pragma unroll
        for (int i = 0; i < 8; i++) {
            int c = tid + 128 * i;          // 64 rows x 16 pairs
            int r = c >> 4;
            int kc = c & 15;
            uint32_t dst = ws_a[b] + (uint32_t)((r * 32 + ((kc ^ (r & 15)) << 1)) * 4);
            cp8(dst, wg + (size_t)r * DDIM + (kc << 1));
        }
        cp_commit();
    };

    ull acc[8][8];
    #pragma unroll
    for (int i = 0; i < 8; i++)
        #pragma unroll
        for (int j = 0; j < 8; j++) acc[i][j] = 0ull;

    load_stage(0, 0);

    #pragma unroll 1
    for (int s = 0; s < NSTAGE; s++) {
        if (s + 1 < NSTAGE) {
            load_stage(s + 1, (s + 1) & 1);
            cp_wait<1>();
        } else {
            cp_wait<0>();
        }
        __syncthreads();

        const float* X  = xs[s & 1];
        const float* Wm = ws[s & 1];
        const float* Xr = X + tm * 32;   // this thread's x row base
        const float* Wr = Wm + tn * 32;  // this thread's w row base

        // Explicit double-buffered operand prefetch: load kp+1 while FFMA2ing kp.
        ull xv[2][8], wv[2][8];

        #define LDKP(KP, BUF)                                                   \
        {                                                                       \
            const ull* xp  = (const ull*)(Xr + (((KP) ^ tm) << 1));             \
            const ull* wp0 = (const ull*)(Wr + (((KP) ^ tn) << 1));             \
            const ull* wp1 = (const ull*)(Wr + (((KP) ^ (tn + 8)) << 1));       \
            _Pragma("unroll")                                                   \
            for (int i = 0; i < 8; i++) xv[BUF][i] = xp[i * 256];               \
            _Pragma("unroll")                                                   \
            for (int j = 0; j < 8; j++)                                         \
                wv[BUF][j] = ((j & 1) ? wp1 : wp0)[j * 128];                    \
        }

        LDKP(0, 0)
        #pragma unroll
        for (int kp = 0; kp < 16; kp++) {
            if (kp + 1 < 16) {
                const int nb = (kp + 1) & 1;
                LDKP(kp + 1, nb)
            }
            const int cb = kp & 1;
            #pragma unroll
            for (int i = 0; i < 8; i++)
                #pragma unroll
                for (int j = 0; j < 8; j++)
                    acc[i][j] = ffma2(xv[cb][i], wv[cb][j], acc[i][j]);
        }
        #undef LDKP
        __syncthreads();
    }

    // ---- epilogue: logits -> smem (stride 65 to kill STS bank conflicts) ----
    float* ls = sm;                 // [128][65]
    float* st = sm + 8320;          // [129] CTA stats
    #pragma unroll
    for (int i = 0; i < 8; i++)
        #pragma unroll
        for (int j = 0; j < 8; j++) {
            float lo = __uint_as_float((uint32_t)(acc[i][j] & 0xffffffffull));
            float hi = __uint_as_float((uint32_t)(acc[i][j] >> 32));
            ls[(tm + 16 * i) * 65 + (tn + 8 * j)] = lo + hi;
        }
    st[tid] = 0.0f;
    if (tid == 0) st[128] = 0.0f;   // block has 128 threads; slot 128 needs explicit zero
    __syncthreads();

    // ---- router: one warp per 32 rows ----
    const int warp = tid >> 5;
    const int lane = tid & 31;
    const float NEG_INF = __int_as_float(0xff800000u);
    float imp0 = 0.f, imp1 = 0.f, cnt0 = 0.f, cnt1 = 0.f, z2 = 0.f;
    float* probs_out = out + PB_OFF;

    #pragma unroll 2
    for (int it = 0; it < 32; it++) {
        const int rl = warp * 32 + it;
        const int row = rowbase + rl;
        const float va = ls[rl * 65 + lane];
        const float vb = ls[rl * 65 + lane + 32];

        // top-1 (ties -> lower index)
        float bv; int bi;
        if (va >= vb) { bv = va; bi = lane; } else { bv = vb; bi = lane + 32; }
        #pragma unroll
        for (int off = 16; off; off >>= 1) {
            float ov = __shfl_xor_sync(0xffffffffu, bv, off);
            int   oi = __shfl_xor_sync(0xffffffffu, bi, off);
            if (ov > bv || (ov == bv && oi < bi)) { bv = ov; bi = oi; }
        }
        // top-2 (exclude bi)
        float va2 = (lane == bi)      ? NEG_INF : va;
        float vb2 = (lane + 32 == bi) ? NEG_INF : vb;
        float sv; int si;
        if (va2 >= vb2) { sv = va2; si = lane; } else { sv = vb2; si = lane + 32; }
        #pragma unroll
        for (int off = 16; off; off >>= 1) {
            float ov = __shfl_xor_sync(0xffffffffu, sv, off);
            int   oi = __shfl_xor_sync(0xffffffffu, si, off);
            if (ov > sv || (ov == sv && oi < si)) { sv = ov; si = oi; }
        }

        // full softmax (max-shifted)
        const float ea = __expf(va - bv);
        const float eb = __expf(vb - bv);
        float ssum = ea + eb;
        #pragma unroll
        for (int off = 16; off; off >>= 1)
            ssum += __shfl_xor_sync(0xffffffffu, ssum, off);
        const float inv = 1.0f / ssum;
        const float pa = ea * inv, pb = eb * inv;

        probs_out[(size_t)row * 64 + lane]      = pa;
        probs_out[(size_t)row * 64 + lane + 32] = pb;

        imp0 += pa; imp1 += pb;
        cnt0 += (bi == lane      ? 1.f : 0.f) + (si == lane      ? 1.f : 0.f);
        cnt1 += (bi == lane + 32 ? 1.f : 0.f) + (si == lane + 32 ? 1.f : 0.f);

        if (lane == 0) {
            const float z = bv + __logf(ssum);
            z2 += z * z;
            out[IDX_OFF + row * 2]     = (float)bi;
            out[IDX_OFF + row * 2 + 1] = (float)si;
            const float e2 = __expf(sv - bv);
            const float dn = 1.0f / (1.0f + e2);
            out[SC_OFF + row * 2]     = dn;
            out[SC_OFF + row * 2 + 1] = e2 * dn;
        }
    }

    // ---- CTA-level stats reduce in smem, then one row of g_part ----
    atomicAdd(&st[lane],      imp0);
    atomicAdd(&st[lane + 32], imp1);
    atomicAdd(&st[64 + lane], cnt0);
    atomicAdd(&st[96 + lane], cnt1);
    if (lane == 0) atomicAdd(&st[128], z2);
    __syncthreads();

    g_part[blockIdx.x][tid] = st[tid];
    if (tid == 0) g_part[blockIdx.x][128] = st[128];   // slot 128 too

    // ---- last-CTA finalize (self-resetting counter) ----
    __shared__ unsigned int s_last;
    __threadfence();
    __syncthreads();
    if (tid == 0) {
        unsigned int old = atomicInc(&g_ctr, NCTA - 1);
        s_last = (old == NCTA - 1) ? 1u : 0u;
    }
    __syncthreads();
    if (s_last) {
        __threadfence();
        #pragma unroll 1
        for (int e = tid; e < 129; e += 128) {
            float ssum = 0.f;
            #pragma unroll 1
            for (int c = 0; c < NCTA; c++) ssum += g_part[c][e];
            if (e < 64)       out[IMP_OFF + e]         = ssum * (1.0f / 16384.0f);
            else if (e < 128) out[LOAD_OFF + (e - 64)] = ssum * (1.0f / 32768.0f);
            else              out[Z_OFF]               = ssum * (1.0f / 16384.0f);
        }
    }
}

extern "C" void kernel_launch(void* const* d_in, const int* in_sizes, int n_in,
                              void* d_out, int out_size) {
    const float* x = (const float*)d_in[0];   // [4,4096,4096] f32
    const float* W = (const float*)d_in[1];   // [64,4096] f32
    float* out = (float*)d_out;
    (void)in_sizes; (void)n_in; (void)out_size;
    router_kernel<<<NCTA, 128>>>(x, W, out);
}

// round 6
// speedup vs baseline: 1.4458x; 1.1929x over previous
#include <cuda_runtime.h>
#include <cstdint>

typedef unsigned long long ull;

// Problem constants
#define DDIM 4096
#define NEXP 64
#define NTOK 16384          // B*S
#define BM   128
#define BK   32
#define NSTAGE (DDIM / BK)  // 128
#define NCTA (NTOK / BM)    // 128

// Output layout (tuple flattened to float32 in reference order)
#define IDX_OFF   0
#define SC_OFF    32768
#define PB_OFF    65536
#define Z_OFF     1114112
#define IMP_OFF   1114113
#define LOAD_OFF  1114177

// Per-CTA partial stats: [0..63] importance, [64..127] counts, [128] z^2
__device__ float g_part[NCTA][129];
__device__ unsigned int g_ctr = 0;   // self-resetting via atomicInc wrap

// ---------- PTX helpers ----------
__device__ __forceinline__ ull ffma2(ull a, ull b, ull c) {
    ull d;
    asm("fma.rn.f32x2 %0, %1, %2, %3;" : "=l"(d) : "l"(a), "l"(b), "l"(c));
    return d;
}
__device__ __forceinline__ void cp16(uint32_t dst, const void* src) {
    asm volatile("cp.async.cg.shared.global [%0], [%1], 16;" :: "r"(dst), "l"(src));
}
__device__ __forceinline__ void cp_commit() {
    asm volatile("cp.async.commit_group;" ::: "memory");
}
template <int N> __device__ __forceinline__ void cp_wait() {
    asm volatile("cp.async.wait_group %0;" :: "n"(N) : "memory");
}

// ---------- single fused kernel ----------
// grid = 128 CTAs (one per 128-token tile), block = 256 threads (2 warps/SMSP).
// Thread tile: 8 rows x 4 experts. Operands via LDS.128 (16B-quad swizzle).
extern "C" __global__ void __launch_bounds__(256, 1)
router_kernel(const float* __restrict__ x, const float* __restrict__ W,
              float* __restrict__ out) {
    // 12288 floats = 48KB static smem.
    //   xs0 [0..4095], ws0 [4096..6143], xs1 [6144..10239], ws1 [10240..12287]
    // After mainloop: ls (128x65 = 8320) at sm[0..8319], stats at sm[8320..8448]
    __shared__ float sm[12288];
    float* xs[2] = { sm,        sm + 6144 };
    float* ws[2] = { sm + 4096, sm + 10240 };
    uint32_t xs_a[2], ws_a[2];
    xs_a[0] = (uint32_t)__cvta_generic_to_shared(xs[0]);
    xs_a[1] = (uint32_t)__cvta_generic_to_shared(xs[1]);
    ws_a[0] = (uint32_t)__cvta_generic_to_shared(ws[0]);
    ws_a[1] = (uint32_t)__cvta_generic_to_shared(ws[1]);

    const int tid = threadIdx.x;
    const int tm = tid & 15;      // row group (16):     rows tm + 16*i, i<8
    const int tn = tid >> 4;      // expert group (16):  experts tn + 16*j, j<4
    const int rowbase = blockIdx.x * BM;

    // ---- stage loader: quad (16B) swizzle — quad q of row r stored at q^(r&7) ----
    auto load_stage = [&](int s, int b) {
        const float* xg = x + (size_t)rowbase * DDIM + s * BK;
        #pragma unroll
        for (int i = 0; i < 4; i++) {
            int c = tid + 256 * i;          // 1024 quads: 128 rows x 8 quads
            int r = c >> 3;
            int q = c & 7;
            uint32_t dst = xs_a[b] + (uint32_t)((r * 32 + ((q ^ (r & 7)) << 2)) * 4);
            cp16(dst, xg + (size_t)r * DDIM + (q << 2));
        }
        const float* wg = W + s * BK;
        #pragma unroll
        for (int i = 0; i < 2; i++) {
            int c = tid + 256 * i;          // 512 quads: 64 rows x 8 quads
            int r = c >> 3;
            int q = c & 7;
            uint32_t dst = ws_a[b] + (uint32_t)((r * 32 + ((q ^ (r & 7)) << 2)) * 4);
            cp16(dst, wg + (size_t)r * DDIM + (q << 2));
        }
        cp_commit();
    };

    ull acc[8][4];
    #pragma unroll
    for (int i = 0; i < 8; i++)
        #pragma unroll
        for (int j = 0; j < 4; j++) acc[i][j] = 0ull;

    load_stage(0, 0);

    const int xo = tm & 7;   // x de-swizzle (row&7 == tm&7 for rows tm+16i)
    const int wo = tn & 7;   // w de-swizzle (row&7 == tn&7 for rows tn+16j)

    #pragma unroll 1
    for (int s = 0; s < NSTAGE; s++) {
        if (s + 1 < NSTAGE) {
            load_stage(s + 1, (s + 1) & 1);
            cp_wait<1>();
        } else {
            cp_wait<0>();
        }
        __syncthreads();

        const float* Xr = xs[s & 1] + tm * 32;
        const float* Wr = ws[s & 1] + tn * 32;

        #pragma unroll
        for (int kq = 0; kq < 8; kq++) {    // 8 quads = 16 k-pairs per stage
            const ulonglong2* xp = (const ulonglong2*)(Xr + ((kq ^ xo) << 2));
            const ulonglong2* wp = (const ulonglong2*)(Wr + ((kq ^ wo) << 2));
            ulonglong2 xv[8], wv[4];
            #pragma unroll
            for (int i = 0; i < 8; i++) xv[i] = xp[i * 128];   // +16 rows (512 floats)
            #pragma unroll
            for (int j = 0; j < 4; j++) wv[j] = wp[j * 128];
            // pair 0 (32 independent FFMA2), then pair 1
            #pragma unroll
            for (int i = 0; i < 8; i++)
                #pragma unroll
                for (int j = 0; j < 4; j++)
                    acc[i][j] = ffma2(xv[i].x, wv[j].x, acc[i][j]);
            #pragma unroll
            for (int i = 0; i < 8; i++)
                #pragma unroll
                for (int j = 0; j < 4; j++)
                    acc[i][j] = ffma2(xv[i].y, wv[j].y, acc[i][j]);
        }
        __syncthreads();
    }

    // ---- epilogue: logits -> smem (stride 65 to kill STS bank conflicts) ----
    float* ls = sm;                 // [128][65]
    float* st = sm + 8320;          // [129] CTA stats
    #pragma unroll
    for (int i = 0; i < 8; i++)
        #pragma unroll
        for (int j = 0; j < 4; j++) {
            float lo = __uint_as_float((uint32_t)(acc[i][j] & 0xffffffffull));
            float hi = __uint_as_float((uint32_t)(acc[i][j] >> 32));
            ls[(tm + 16 * i) * 65 + (tn + 16 * j)] = lo + hi;
        }
    if (tid < 129) st[tid] = 0.0f;
    __syncthreads();

    // ---- router: 8 warps, 16 rows per warp ----
    const int warp = tid >> 5;
    const int lane = tid & 31;
    const float NEG_INF = __int_as_float(0xff800000u);
    float imp0 = 0.f, imp1 = 0.f, cnt0 = 0.f, cnt1 = 0.f, z2 = 0.f;
    float* probs_out = out + PB_OFF;

    #pragma unroll 2
    for (int it = 0; it < 16; it++) {
        const int rl = warp * 16 + it;
        const int row = rowbase + rl;
        const float va = ls[rl * 65 + lane];
        const float vb = ls[rl * 65 + lane + 32];

        // top-1 (ties -> lower index)
        float bv; int bi;
        if (va >= vb) { bv = va; bi = lane; } else { bv = vb; bi = lane + 32; }
        #pragma unroll
        for (int off = 16; off; off >>= 1) {
            float ov = __shfl_xor_sync(0xffffffffu, bv, off);
            int   oi = __shfl_xor_sync(0xffffffffu, bi, off);
            if (ov > bv || (ov == bv && oi < bi)) { bv = ov; bi = oi; }
        }
        // top-2 (exclude bi)
        float va2 = (lane == bi)      ? NEG_INF : va;
        float vb2 = (lane + 32 == bi) ? NEG_INF : vb;
        float sv; int si;
        if (va2 >= vb2) { sv = va2; si = lane; } else { sv = vb2; si = lane + 32; }
        #pragma unroll
        for (int off = 16; off; off >>= 1) {
            float ov = __shfl_xor_sync(0xffffffffu, sv, off);
            int   oi = __shfl_xor_sync(0xffffffffu, si, off);
            if (ov > sv || (ov == sv && oi < si)) { sv = ov; si = oi; }
        }

        // full softmax (max-shifted)
        const float ea = __expf(va - bv);
        const float eb = __expf(vb - bv);
        float ssum = ea + eb;
        #pragma unroll
        for (int off = 16; off; off >>= 1)
            ssum += __shfl_xor_sync(0xffffffffu, ssum, off);
        const float inv = 1.0f / ssum;
        const float pa = ea * inv, pb = eb * inv;

        probs_out[(size_t)row * 64 + lane]      = pa;
        probs_out[(size_t)row * 64 + lane + 32] = pb;

        imp0 += pa; imp1 += pb;
        cnt0 += (bi == lane      ? 1.f : 0.f) + (si == lane      ? 1.f : 0.f);
        cnt1 += (bi == lane + 32 ? 1.f : 0.f) + (si == lane + 32 ? 1.f : 0.f);

        if (lane == 0) {
            const float z = bv + __logf(ssum);
            z2 += z * z;
            out[IDX_OFF + row * 2]     = (float)bi;
            out[IDX_OFF + row * 2 + 1] = (float)si;
            const float e2 = __expf(sv - bv);
            const float dn = 1.0f / (1.0f + e2);
            out[SC_OFF + row * 2]     = dn;
            out[SC_OFF + row * 2 + 1] = e2 * dn;
        }
    }

    // ---- CTA-level stats reduce in smem, then one row of g_part ----
    atomicAdd(&st[lane],      imp0);
    atomicAdd(&st[lane + 32], imp1);
    atomicAdd(&st[64 + lane], cnt0);
    atomicAdd(&st[96 + lane], cnt1);
    if (lane == 0) atomicAdd(&st[128], z2);
    __syncthreads();

    if (tid < 129) g_part[blockIdx.x][tid] = st[tid];

    // ---- last-CTA finalize (self-resetting counter) ----
    __shared__ unsigned int s_last;
    __threadfence();
    __syncthreads();
    if (tid == 0) {
        unsigned int old = atomicInc(&g_ctr, NCTA - 1);
        s_last = (old == NCTA - 1) ? 1u : 0u;
    }
    __syncthreads();
    if (s_last && tid < 129) {
        __threadfence();
        float ssum = 0.f;
        #pragma unroll 1
        for (int c = 0; c < NCTA; c++) ssum += g_part[c][tid];
        if (tid < 64)       out[IMP_OFF + tid]         = ssum * (1.0f / 16384.0f);
        else if (tid < 128) out[LOAD_OFF + (tid - 64)] = ssum * (1.0f / 32768.0f);
        else                out[Z_OFF]                 = ssum * (1.0f / 16384.0f);
    }
}

extern "C" void kernel_launch(void* const* d_in, const int* in_sizes, int n_in,
                              void* d_out, int out_size) {
    const float* x = (const float*)d_in[0];   // [4,4096,4096] f32
    const float* W = (const float*)d_in[1];   // [64,4096] f32
    float* out = (float*)d_out;
    (void)in_sizes; (void)n_in; (void)out_size;
    router_kernel<<<NCTA, 256>>>(x, W, out);
}